// round 15
// baseline (speedup 1.0000x reference)
#include <cuda_runtime.h>
#include <cuda_fp16.h>
#include <math.h>

#define D_INF   128
#define D_OUTF  128
#define KNOTS   64
#define NBATCH  4096
#define EPSF    1e-12f
#define BPB     4      // batches per block (2 warps per batch, i-halves)
#define FULLMASK 0xffffffffu

// Interleaved fp16 table: [i][k][o][(ct,dt)] — one half2 per (i,k,o).
// Row (i,k) = 128 half2 = 512B = 32 uint4 units; lane owns o-quad = 1 uint4.
__device__ uint4 g_t4[D_INF * KNOTS * 32];

__device__ __forceinline__ __half2 h2(unsigned u) {
    return *reinterpret_cast<const __half2*>(&u);
}
__device__ __forceinline__ unsigned h2u(__half2 h) {
    return *reinterpret_cast<unsigned*>(&h);
}

// ---------------------------------------------------------------------------
// Kernel 1: PCHIP slopes + transpose into interleaved (ct,dt) fp16 table.
// grid = 128 (i), block = 512 = (o:128, q:4); each thread owns 16 k's.
// All math fp32; single combined half2 store per (k,o) — fully coalesced.
// ---------------------------------------------------------------------------
__global__ __launch_bounds__(512) void kan_preprocess(
    const float* __restrict__ coeffs,   // [D_OUT][D_IN][K]
    const float* __restrict__ knots)    // [K]
{
    __shared__ float ybuf[D_OUTF][KNOTS + 1];   // +1 pad
    __shared__ float h_s[KNOTS];
    __shared__ float rh_s[KNOTS];

    const int tid = threadIdx.x;
    const int i   = blockIdx.x;
    const int o   = tid & 127;
    const int q   = tid >> 7;

    if (tid < KNOTS - 1) {
        float h = knots[tid + 1] - knots[tid];
        h_s[tid]  = h;
        rh_s[tid] = 1.0f / (h + EPSF);
    }
    for (int j = tid; j < D_OUTF * KNOTS; j += 512) {
        int oo = j >> 6;
        int kk = j & (KNOTS - 1);
        ybuf[oo][kk] = coeffs[(oo * D_INF + i) * KNOTS + kk];
    }
    __syncthreads();

    const float* y = ybuf[o];
    __half2* T2 = reinterpret_cast<__half2*>(g_t4);
    const int k0 = q * 16;

    // deltas del[kk] = delta[k0-1+kk], kk = 0..16
    float del[17];
    #pragma unroll
    for (int kk = 0; kk < 17; ++kk) {
        int k = k0 - 1 + kk;
        del[kk] = (k >= 0 && k < KNOTS - 1) ? (y[k + 1] - y[k]) * rh_s[k] : 0.f;
    }

    #pragma unroll
    for (int kk = 0; kk < 16; ++kk) {
        int k = k0 + kk;
        float dd;
        if (k == 0) {
            float delta0 = del[1];
            float delta1 = del[2];
            float df = __fdividef((2.f * h_s[0] + h_s[1]) * delta0 - h_s[0] * delta1,
                                  h_s[0] + h_s[1] + EPSF);
            df = (df * delta0 <= 0.f) ? 0.f : df;
            df = (fabsf(df) > 3.f * fabsf(delta0)) ? 3.f * delta0 : df;
            dd = df;
        } else if (k == KNOTS - 1) {
            float delta62 = del[15];
            float delta61 = del[14];
            float dl = __fdividef((2.f * h_s[KNOTS - 2] + h_s[KNOTS - 3]) * delta62 -
                                  h_s[KNOTS - 2] * delta61,
                                  h_s[KNOTS - 2] + h_s[KNOTS - 3] + EPSF);
            dl = (dl * delta62 <= 0.f) ? 0.f : dl;
            dl = (fabsf(dl) > 3.f * fabsf(delta62)) ? 3.f * delta62 : dl;
            dd = dl;
        } else {
            float dprev = del[kk];
            float dcur  = del[kk + 1];
            float h0 = h_s[k - 1], h1 = h_s[k];
            float w1 = 2.f * h1 + h0;
            float w2 = h1 + 2.f * h0;
            float dpe = dprev + EPSF;
            float dce = dcur + EPSF;
            float num = (w1 + w2) * dpe * dce;
            float den = w1 * dce + w2 * dpe + EPSF * dpe * dce;
            dd = (dprev * dcur > 0.f) ? __fdividef(num, den) : 0.f;
        }
        T2[(i * KNOTS + k) * D_OUTF + o] =
            __halves2half2(__float2half(y[k]), __float2half(dd));
    }
}

// ---------------------------------------------------------------------------
// Kernel 2: main evaluation. Compacted ext/interior lists padded to x4;
// ext iter = 1 LDG.128 + 4 HFMA2; interior = 2 LDG.128 + 8 HFMA2.
// half2 accumulators (ct-stream low, dt-stream high) flushed to float2
// every 4 iterations; horizontal sum once at the end.
// ---------------------------------------------------------------------------
__global__ __launch_bounds__(256) void kan_main(
    const float* __restrict__ x,      // [B][D_IN]
    const float* __restrict__ bias,   // [D_OUT]
    float* __restrict__ out)          // [B][D_OUT]
{
    __shared__ uint2 erec[BPB][2][64];    // {rowbase(uint4 units), w01}
    __shared__ uint4 irec[BPB][2][64];    // {rowbase, w01, w23, 0}
    __shared__ int   cnt[BPB][2][2];      // [bl][half][ext|int]
    __shared__ float4 part[BPB][32];

    const int tid  = threadIdx.x;
    const int lane = tid & 31;
    const int b0   = blockIdx.x * BPB;
    const float hf = 1.0f / (float)(KNOTS - 1);

    if (tid < BPB * 2 * 2) ((int*)cnt)[tid] = 0;
    __syncthreads();

    // -------- Phase 1: classify + compact ---------------------------------
    for (int p = tid; p < BPB * D_INF; p += 256) {
        int bl   = p >> 7;
        int i    = p & (D_INF - 1);
        int half = i >> 6;
        float xv = x[(b0 + bl) * D_INF + i];

        bool ext = (xv < 0.0f) | (xv > 1.0f);
        int idx;
        float w0, w1, w2, w3;
        if (xv < 0.0f) {
            idx = 0;          w0 = 1.f; w1 = xv;        w2 = 0.f; w3 = 0.f;
        } else if (xv > 1.0f) {
            idx = KNOTS - 1;  w0 = 1.f; w1 = xv - 1.0f; w2 = 0.f; w3 = 0.f;
        } else {
            idx = (int)floorf(xv * (float)(KNOTS - 1));
            if (idx > KNOTS - 2) idx = KNOTS - 2;
            float t  = (xv - (float)idx * hf) * (float)(KNOTS - 1);
            float t2 = t * t;
            float t3 = t2 * t;
            w0 = 2.f * t3 - 3.f * t2 + 1.f;
            w1 = (t3 - 2.f * t2 + t) * hf;
            w2 = -2.f * t3 + 3.f * t2;
            w3 = (t3 - t2) * hf;
        }
        unsigned w01 = h2u(__halves2half2(__float2half(w0), __float2half(w1)));
        unsigned w23 = h2u(__halves2half2(__float2half(w2), __float2half(w3)));

        unsigned m  = __ballot_sync(FULLMASK, ext);
        int nE = __popc(m);
        int baseE = 0, baseI = 0;
        if (lane == 0) {
            baseE = atomicAdd(&cnt[bl][half][0], nE);
            baseI = atomicAdd(&cnt[bl][half][1], 32 - nE);
        }
        baseE = __shfl_sync(FULLMASK, baseE, 0);
        baseI = __shfl_sync(FULLMASK, baseI, 0);
        unsigned ltm = (1u << lane) - 1u;
        int rankE = __popc(m & ltm);
        int rankI = lane - rankE;
        int rowbase = ((i << 6) + idx) << 5;   // (i*64+idx) * 32 uint4-units

        if (ext) {
            erec[bl][half][baseE + rankE] = make_uint2(rowbase, w01);
        } else {
            irec[bl][half][baseI + rankI] = make_uint4(rowbase, w01, w23, 0);
        }
    }
    __syncthreads();

    // Pad lists to multiples of 4 with zero-weight dummies (row 0, w=0).
    if (tid < BPB * 2) {
        int bl = tid >> 1, hfx = tid & 1;
        int nE = cnt[bl][hfx][0];
        for (int s = nE; s < ((nE + 3) & ~3); ++s)
            erec[bl][hfx][s] = make_uint2(0, 0);
        int nI = cnt[bl][hfx][1];
        for (int s = nI; s < ((nI + 3) & ~3); ++s)
            irec[bl][hfx][s] = make_uint4(0, 0, 0, 0);
    }
    __syncthreads();

    // -------- Phase 2: gather + accumulate --------------------------------
    const int warp = tid >> 5;
    const int bl   = warp >> 1;
    const int half = warp & 1;
    const int nE4 = (cnt[bl][half][0] + 3) & ~3;
    const int nI4 = (cnt[bl][half][1] + 3) & ~3;

    const uint4* __restrict__ T4 = g_t4;
    const __half2 zero2 = __float2half2_rn(0.f);

    float2 f0 = make_float2(0.f, 0.f), f1 = f0, f2 = f0, f3 = f0;

    for (int j = 0; j < nE4; j += 4) {
        __half2 a0 = zero2, a1 = zero2, a2 = zero2, a3 = zero2;
        #pragma unroll
        for (int u = 0; u < 4; ++u) {
            uint2 rec = erec[bl][half][j + u];
            uint4 v = __ldg(&T4[rec.x + lane]);
            __half2 w = h2(rec.y);
            a0 = __hfma2(h2(v.x), w, a0);
            a1 = __hfma2(h2(v.y), w, a1);
            a2 = __hfma2(h2(v.z), w, a2);
            a3 = __hfma2(h2(v.w), w, a3);
        }
        float2 t;
        t = __half22float2(a0); f0.x += t.x; f0.y += t.y;
        t = __half22float2(a1); f1.x += t.x; f1.y += t.y;
        t = __half22float2(a2); f2.x += t.x; f2.y += t.y;
        t = __half22float2(a3); f3.x += t.x; f3.y += t.y;
    }

    for (int j = 0; j < nI4; j += 4) {
        __half2 a0 = zero2, a1 = zero2, a2 = zero2, a3 = zero2;
        #pragma unroll
        for (int u = 0; u < 4; ++u) {
            uint4 rec = irec[bl][half][j + u];
            uint4 v0 = __ldg(&T4[rec.x + lane]);        // knot k
            uint4 v1 = __ldg(&T4[rec.x + 32 + lane]);   // knot k+1
            __half2 wA = h2(rec.y);
            __half2 wB = h2(rec.z);
            a0 = __hfma2(h2(v0.x), wA, a0);
            a1 = __hfma2(h2(v0.y), wA, a1);
            a2 = __hfma2(h2(v0.z), wA, a2);
            a3 = __hfma2(h2(v0.w), wA, a3);
            a0 = __hfma2(h2(v1.x), wB, a0);
            a1 = __hfma2(h2(v1.y), wB, a1);
            a2 = __hfma2(h2(v1.z), wB, a2);
            a3 = __hfma2(h2(v1.w), wB, a3);
        }
        float2 t;
        t = __half22float2(a0); f0.x += t.x; f0.y += t.y;
        t = __half22float2(a1); f1.x += t.x; f1.y += t.y;
        t = __half22float2(a2); f2.x += t.x; f2.y += t.y;
        t = __half22float2(a3); f3.x += t.x; f3.y += t.y;
    }

    // Horizontal sum (ct-stream + dt-stream) per o.
    float4 acc = make_float4(f0.x + f0.y, f1.x + f1.y,
                             f2.x + f2.y, f3.x + f3.y);

    // Combine i-halves; add bias; write.
    if (half) {
        part[bl][lane] = acc;
    }
    __syncthreads();
    if (!half) {
        float4 pv = part[bl][lane];
        float4 bb = __ldg(&reinterpret_cast<const float4*>(bias)[lane]);
        acc.x += pv.x + bb.x;
        acc.y += pv.y + bb.y;
        acc.z += pv.z + bb.z;
        acc.w += pv.w + bb.w;
        reinterpret_cast<float4*>(out)[(b0 + bl) * (D_OUTF / 4) + lane] = acc;
    }
}

// ---------------------------------------------------------------------------
// Launch
// ---------------------------------------------------------------------------
extern "C" void kernel_launch(void* const* d_in, const int* in_sizes, int n_in,
                              void* d_out, int out_size)
{
    const float* x      = (const float*)d_in[0];  // [4096,128]
    const float* coeffs = (const float*)d_in[1];  // [128,128,64]
    const float* bias   = (const float*)d_in[2];  // [128]
    const float* knots  = (const float*)d_in[3];  // [64]
    float* out = (float*)d_out;                   // [4096,128]

    kan_preprocess<<<D_INF, 512>>>(coeffs, knots);
    kan_main<<<NBATCH / BPB, 256>>>(x, bias, out);
}